// round 3
// baseline (speedup 1.0000x reference)
#include <cuda_runtime.h>
#include <cuda_bf16.h>
#include <math.h>

// ---------------------------------------------------------------------------
// GCN node classifier:
//   deg/dinv from edge targets (+self loop), CSR by destination,
//   per layer: G = rowscale(dinv) * (X @ W);  Y[v] = relu(dinv[v]*(G[v] + sum_{u->v} G[u]) + b)
//   head: OUT = Y @ Wl + bl
// edge_index arrives as int32 (JAX x64 disabled: randint int64 -> int32).
// No host-side symbol queries; device globals referenced in device code only.
// ---------------------------------------------------------------------------

#define N_NODES 40000
#define C_FEAT  128
#define N_EDGES 640000

// Scratch (device globals: no allocation allowed in kernel_launch)
__device__ float d_g[(size_t)N_NODES * C_FEAT];   // GEMM output (dinv-scaled)
__device__ float d_y[(size_t)N_NODES * C_FEAT];   // aggregated/activated features
__device__ int   d_cnt[N_NODES];
__device__ int   d_off[N_NODES + 1];
__device__ int   d_cursor[N_NODES];
__device__ int   d_adj[N_EDGES];
__device__ float d_dinv[N_NODES];

// ---------------------------------------------------------------------------
__global__ void zero_cnt_kernel() {
    int i = blockIdx.x * blockDim.x + threadIdx.x;
    if (i < N_NODES) d_cnt[i] = 0;
}

__global__ void hist_kernel(const int* __restrict__ ei, int E) {
    int e = blockIdx.x * blockDim.x + threadIdx.x;
    if (e < E) {
        int v = ei[E + e];  // col = target
        atomicAdd(&d_cnt[v], 1);
    }
}

// Single-block exclusive scan over 40000 counts; also emits cursor copy and dinv.
__global__ void scan_kernel() {
    __shared__ int part[1025];
    const int T = 1024;
    int tid = threadIdx.x;
    const int per = (N_NODES + T - 1) / T;  // 40
    int s0 = tid * per;
    int s1 = s0 + per; if (s1 > N_NODES) s1 = N_NODES;
    int sum = 0;
    for (int i = s0; i < s1; i++) sum += d_cnt[i];
    part[tid] = sum;
    __syncthreads();
    if (tid == 0) {
        int r = 0;
        for (int i = 0; i < T; i++) { int v = part[i]; part[i] = r; r += v; }
        part[T] = r;
    }
    __syncthreads();
    int run = part[tid];
    for (int i = s0; i < s1; i++) {
        int c = d_cnt[i];
        d_off[i] = run;
        d_cursor[i] = run;
        d_dinv[i] = rsqrtf((float)(c + 1));  // +1 self loop; always > 0
        run += c;
    }
    if (tid == T - 1) d_off[N_NODES] = part[T];
}

__global__ void scatter_kernel(const int* __restrict__ ei, int E) {
    int e = blockIdx.x * blockDim.x + threadIdx.x;
    if (e < E) {
        int v = ei[E + e];      // target
        int r = ei[e];          // source
        int p = atomicAdd(&d_cursor[v], 1);
        d_adj[p] = r;
    }
}

// ---------------------------------------------------------------------------
// Register-tiled SGEMM: A[M,128] @ B[128,BN] -> C[M,BN]
// BM=64, BK=16, per-thread 4x8.  Optional per-row scale (dinv) and per-col bias.
// M = 40000 is an exact multiple of BM, so no row guards.
// a_sel: 0 = Aext, 1 = d_y.   c_sel: 0 = Cext, 1 = d_g.
// use_rowscale: multiply rows by d_dinv.  bias may be null.
// ---------------------------------------------------------------------------
template <int BN>
__global__ void gemm_kernel(const float* __restrict__ Aext,
                            const float* __restrict__ B,
                            const float* __restrict__ bias,
                            float* __restrict__ Cext,
                            int a_sel, int c_sel, int use_rowscale) {
    constexpr int BM = 64, BK = 16, TM = 4;
    constexpr int NCG = BN / 8;           // column groups (threads in x)
    constexpr int NT  = 16 * NCG;         // total threads
    __shared__ __align__(16) float As[BK][BM + 4];
    __shared__ __align__(16) float Bs[BK][BN];

    const float* A = (a_sel == 0) ? Aext : (const float*)d_y;
    float*       C = (c_sel == 0) ? Cext : (float*)d_g;

    int tid = threadIdx.x;
    int tx = tid % NCG;       // 0..NCG-1
    int ty = tid / NCG;       // 0..15
    int row0 = blockIdx.x * BM;

    float acc[TM][8];
#pragma unroll
    for (int i = 0; i < TM; i++)
#pragma unroll
        for (int j = 0; j < 8; j++) acc[i][j] = 0.f;

    for (int k0 = 0; k0 < C_FEAT; k0 += BK) {
        // Load A tile (64x16) as float4, store transposed
        for (int i = tid; i < BM * BK / 4; i += NT) {
            int r = i >> 2;
            int c4 = i & 3;
            float4 v = *(const float4*)&A[(size_t)(row0 + r) * C_FEAT + k0 + c4 * 4];
            As[c4 * 4 + 0][r] = v.x;
            As[c4 * 4 + 1][r] = v.y;
            As[c4 * 4 + 2][r] = v.z;
            As[c4 * 4 + 3][r] = v.w;
        }
        // Load B tile (16xBN) directly
        for (int i = tid; i < BK * BN / 4; i += NT) {
            int r = i / (BN / 4);
            int c = i % (BN / 4);
            *(float4*)&Bs[r][c * 4] = *(const float4*)&B[(size_t)(k0 + r) * BN + c * 4];
        }
        __syncthreads();
#pragma unroll
        for (int kk = 0; kk < BK; kk++) {
            float4 a  = *(const float4*)&As[kk][ty * 4];
            float4 b0 = *(const float4*)&Bs[kk][tx * 4];
            float4 b1 = *(const float4*)&Bs[kk][BN / 2 + tx * 4];
            float av[4] = {a.x, a.y, a.z, a.w};
            float bv[8] = {b0.x, b0.y, b0.z, b0.w, b1.x, b1.y, b1.z, b1.w};
#pragma unroll
            for (int i = 0; i < TM; i++)
#pragma unroll
                for (int j = 0; j < 8; j++)
                    acc[i][j] = fmaf(av[i], bv[j], acc[i][j]);
        }
        __syncthreads();
    }

    float4 bb0 = make_float4(0.f, 0.f, 0.f, 0.f), bb1 = bb0;
    if (bias) {
        bb0 = *(const float4*)&bias[tx * 4];
        bb1 = *(const float4*)&bias[BN / 2 + tx * 4];
    }
#pragma unroll
    for (int i = 0; i < TM; i++) {
        int r = row0 + ty * 4 + i;
        float s = use_rowscale ? d_dinv[r] : 1.0f;
        float4 o0 = make_float4(fmaf(acc[i][0], s, bb0.x), fmaf(acc[i][1], s, bb0.y),
                                fmaf(acc[i][2], s, bb0.z), fmaf(acc[i][3], s, bb0.w));
        float4 o1 = make_float4(fmaf(acc[i][4], s, bb1.x), fmaf(acc[i][5], s, bb1.y),
                                fmaf(acc[i][6], s, bb1.z), fmaf(acc[i][7], s, bb1.w));
        *(float4*)&C[(size_t)r * BN + tx * 4] = o0;
        *(float4*)&C[(size_t)r * BN + BN / 2 + tx * 4] = o1;
    }
}

// ---------------------------------------------------------------------------
// Aggregation: one warp per node. y[v] = relu(dinv[v]*(g[v] + sum g[u]) + b)
// Each lane owns 4 channels (float4). Adjacency fetched coalesced in batches
// of 32 and broadcast via shfl so gather loads can overlap.
// ---------------------------------------------------------------------------
__global__ void agg_kernel(const float* __restrict__ bias) {
    int gw = (blockIdx.x * blockDim.x + threadIdx.x) >> 5;
    if (gw >= N_NODES) return;
    int lane = threadIdx.x & 31;
    int c = lane << 2;

    float4 acc = *(const float4*)&d_g[(size_t)gw * C_FEAT + c];  // self loop
    int s = d_off[gw], e = d_off[gw + 1];
    for (int base = s; base < e; base += 32) {
        int n = e - base;
        int m = n < 32 ? n : 32;
        int myu = (lane < m) ? d_adj[base + lane] : 0;
        for (int j = 0; j < m; j++) {
            int u = __shfl_sync(0xffffffffu, myu, j);
            float4 t = *(const float4*)&d_g[(size_t)u * C_FEAT + c];
            acc.x += t.x; acc.y += t.y; acc.z += t.z; acc.w += t.w;
        }
    }
    float dv = d_dinv[gw];
    float4 bb = *(const float4*)&bias[c];
    float4 o;
    o.x = fmaxf(fmaf(acc.x, dv, bb.x), 0.f);
    o.y = fmaxf(fmaf(acc.y, dv, bb.y), 0.f);
    o.z = fmaxf(fmaf(acc.z, dv, bb.z), 0.f);
    o.w = fmaxf(fmaf(acc.w, dv, bb.w), 0.f);
    *(float4*)&d_y[(size_t)gw * C_FEAT + c] = o;
}

// ---------------------------------------------------------------------------
extern "C" void kernel_launch(void* const* d_in, const int* in_sizes, int n_in,
                              void* d_out, int out_size) {
    const float* x  = (const float*)d_in[0];
    const int*   ei = (const int*)d_in[1];     // int32! JAX x64 is disabled.
    const float* W1 = (const float*)d_in[2];
    const float* b1 = (const float*)d_in[3];
    const float* W2 = (const float*)d_in[4];
    const float* b2 = (const float*)d_in[5];
    const float* Wl = (const float*)d_in[6];
    const float* bl = (const float*)d_in[7];
    float* out = (float*)d_out;

    int E = in_sizes[1] / 2;   // 640000

    // CSR build
    zero_cnt_kernel<<<(N_NODES + 255) / 256, 256>>>();
    hist_kernel<<<(E + 255) / 256, 256>>>(ei, E);
    scan_kernel<<<1, 1024>>>();
    scatter_kernel<<<(E + 255) / 256, 256>>>(ei, E);

    const int gemm_grid = N_NODES / 64;                 // 625
    const int agg_grid  = (N_NODES * 32 + 255) / 256;   // 5000 (warp/node, 8 warps/CTA)

    // Layer 1: A = x (ext), C = d_g, rowscale on
    gemm_kernel<128><<<gemm_grid, 256>>>(x, W1, nullptr, nullptr, 0, 1, 1);
    agg_kernel<<<agg_grid, 256>>>(b1);
    // Layer 2: A = d_y, C = d_g, rowscale on
    gemm_kernel<128><<<gemm_grid, 256>>>(nullptr, W2, nullptr, nullptr, 1, 1, 1);
    agg_kernel<<<agg_grid, 256>>>(b2);
    // Head: A = d_y, C = out, bias, no rowscale
    gemm_kernel<64><<<gemm_grid, 128>>>(nullptr, Wl, bl, out, 1, 0, 0);
}

// round 4
// speedup vs baseline: 1.1679x; 1.1679x over previous
#include <cuda_runtime.h>
#include <cuda_bf16.h>
#include <math.h>
#include <stdint.h>

// ---------------------------------------------------------------------------
// GCN node classifier, tf32 tensor-core GEMM version.
//   CSR by destination (+implicit self loop), dinv = rsqrt(deg+1).
//   layer: G = rowscale(dinv)*(X @ W);  Y[v] = relu(dinv[v]*(G[v]+sum_{u->v}G[u]) + b)
//   head:  OUT = Y @ Wl + bl
// edge_index is int32. No host-side symbol queries (graph-capture safe).
// ---------------------------------------------------------------------------

#define N_NODES 40000
#define C_FEAT  128
#define N_EDGES 640000

__device__ float d_g[(size_t)N_NODES * C_FEAT];
__device__ float d_y[(size_t)N_NODES * C_FEAT];
__device__ int   d_cnt[N_NODES];
__device__ int   d_off[N_NODES + 1];
__device__ int   d_cursor[N_NODES];
__device__ int   d_adj[N_EDGES];
__device__ float d_dinv[N_NODES];

// ---------------------------------------------------------------------------
__global__ void zero_cnt_kernel() {
    int i = blockIdx.x * blockDim.x + threadIdx.x;
    if (i < N_NODES) d_cnt[i] = 0;
}

__global__ void hist_kernel(const int* __restrict__ ei, int E) {
    int e = blockIdx.x * blockDim.x + threadIdx.x;
    if (e < E) atomicAdd(&d_cnt[ei[E + e]], 1);
}

// 1024-thread block; warp-shuffle hierarchical exclusive scan over 40000 counts.
__global__ void scan_kernel() {
    __shared__ int wsum[32];
    const int T = 1024;
    int tid = threadIdx.x;
    int lane = tid & 31, wid = tid >> 5;
    const int per = (N_NODES + T - 1) / T;  // 40
    int s0 = tid * per;
    int s1 = s0 + per; if (s1 > N_NODES) s1 = N_NODES;
    int sum = 0;
    for (int i = s0; i < s1; i++) sum += d_cnt[i];

    // warp inclusive scan
    int v = sum;
#pragma unroll
    for (int d = 1; d < 32; d <<= 1) {
        int t = __shfl_up_sync(0xffffffffu, v, d);
        if (lane >= d) v += t;
    }
    if (lane == 31) wsum[wid] = v;
    __syncthreads();
    if (wid == 0) {
        int ow = wsum[lane];
        int iv = ow;
#pragma unroll
        for (int d = 1; d < 32; d <<= 1) {
            int t = __shfl_up_sync(0xffffffffu, iv, d);
            if (lane >= d) iv += t;
        }
        wsum[lane] = iv - ow;  // exclusive warp offsets
    }
    __syncthreads();
    int run = (v - sum) + wsum[wid];  // exclusive prefix for this thread
    for (int i = s0; i < s1; i++) {
        int c = d_cnt[i];
        d_off[i] = run;
        d_cursor[i] = run;
        d_dinv[i] = rsqrtf((float)(c + 1));
        run += c;
    }
    if (tid == T - 1) d_off[N_NODES] = run;
}

__global__ void scatter_kernel(const int* __restrict__ ei, int E) {
    int e = blockIdx.x * blockDim.x + threadIdx.x;
    if (e < E) {
        int v = ei[E + e];
        int r = ei[e];
        int p = atomicAdd(&d_cursor[v], 1);
        d_adj[p] = r;
    }
}

// ---------------------------------------------------------------------------
// tf32 tensor-core GEMM: C[M,BN] = A[M,128] @ B[128,BN]
// CTA: 128 rows x BN cols, 8 warps. Warp tile: 32 x (BN/2).
// K staged in chunks of 32 through padded smem (conflict-free frag loads).
// a_sel: 0=Aext 1=d_y.  c_sel: 0=Cext 1=d_g.
// ---------------------------------------------------------------------------
__device__ __forceinline__ uint32_t f2tf(float f) {
    uint32_t r;
    asm("cvt.rna.tf32.f32 %0, %1;" : "=r"(r) : "f"(f));
    return r;
}

template <int BN>
__global__ void __launch_bounds__(256, 2)
gemm_tf32_kernel(const float* __restrict__ Aext,
                 const float* __restrict__ B,
                 const float* __restrict__ bias,
                 float* __restrict__ Cext,
                 int a_sel, int c_sel, int use_rowscale) {
    constexpr int BM = 128, KC = 32, NKC = C_FEAT / KC;   // 4 chunks
    constexpr int AP = 36;            // A smem k-stride (words)
    constexpr int NP = BN + 4;        // B smem n-stride (words)
    constexpr int WN = BN / 2;        // warp n extent
    constexpr int MF = 2;             // 32 rows / 16
    constexpr int NF = WN / 8;        // n frags

    __shared__ uint32_t As[BM * AP];  // [m][k] tf32
    __shared__ uint32_t Bs[KC * NP];  // [k][n] tf32

    const float* A = (a_sel == 0) ? Aext : (const float*)d_y;
    float*       C = (c_sel == 0) ? Cext : (float*)d_g;

    int tid = threadIdx.x;
    int lane = tid & 31;
    int wid = tid >> 5;
    int warp_m = wid & 3;             // 0..3
    int warp_n = wid >> 2;            // 0..1
    int qid = lane >> 2;              // 0..7
    int qt = lane & 3;                // 0..3
    int row0 = blockIdx.x * BM;

    float acc[MF][NF][4];
#pragma unroll
    for (int i = 0; i < MF; i++)
#pragma unroll
        for (int j = 0; j < NF; j++)
#pragma unroll
            for (int k = 0; k < 4; k++) acc[i][j][k] = 0.f;

    for (int kc = 0; kc < NKC; kc++) {
        int k0 = kc * KC;
        // --- stage A chunk: 128 rows x 32 k, cvt to tf32 ---
        for (int i = tid; i < BM * (KC / 4); i += 256) {
            int r = i >> 3;           // KC/4 = 8 vectors per row
            int vv = i & 7;
            int gr = row0 + r; if (gr > N_NODES - 1) gr = N_NODES - 1;
            float4 v = *(const float4*)&A[(size_t)gr * C_FEAT + k0 + vv * 4];
            uint32_t* dst = &As[r * AP + vv * 4];
            dst[0] = f2tf(v.x); dst[1] = f2tf(v.y);
            dst[2] = f2tf(v.z); dst[3] = f2tf(v.w);
        }
        // --- stage B chunk: 32 k x BN n ---
        for (int i = tid; i < KC * (BN / 4); i += 256) {
            int r = i / (BN / 4);
            int vv = i % (BN / 4);
            float4 v = *(const float4*)&B[(size_t)(k0 + r) * BN + vv * 4];
            uint32_t* dst = &Bs[r * NP + vv * 4];
            dst[0] = f2tf(v.x); dst[1] = f2tf(v.y);
            dst[2] = f2tf(v.z); dst[3] = f2tf(v.w);
        }
        __syncthreads();

#pragma unroll
        for (int k8 = 0; k8 < KC / 8; k8++) {
            int kb = k8 * 8;
            uint32_t af[MF][4];
#pragma unroll
            for (int im = 0; im < MF; im++) {
                int m0 = warp_m * 32 + im * 16 + qid;
                af[im][0] = As[m0 * AP + kb + qt];
                af[im][1] = As[(m0 + 8) * AP + kb + qt];
                af[im][2] = As[m0 * AP + kb + qt + 4];
                af[im][3] = As[(m0 + 8) * AP + kb + qt + 4];
            }
            uint32_t bf[NF][2];
#pragma unroll
            for (int jn = 0; jn < NF; jn++) {
                int n0 = warp_n * WN + jn * 8 + qid;
                bf[jn][0] = Bs[(kb + qt) * NP + n0];
                bf[jn][1] = Bs[(kb + qt + 4) * NP + n0];
            }
#pragma unroll
            for (int im = 0; im < MF; im++)
#pragma unroll
                for (int jn = 0; jn < NF; jn++) {
                    asm volatile(
                        "mma.sync.aligned.m16n8k8.row.col.f32.tf32.tf32.f32 "
                        "{%0,%1,%2,%3}, {%4,%5,%6,%7}, {%8,%9}, {%0,%1,%2,%3};\n"
                        : "+f"(acc[im][jn][0]), "+f"(acc[im][jn][1]),
                          "+f"(acc[im][jn][2]), "+f"(acc[im][jn][3])
                        : "r"(af[im][0]), "r"(af[im][1]), "r"(af[im][2]), "r"(af[im][3]),
                          "r"(bf[jn][0]), "r"(bf[jn][1]));
                }
        }
        __syncthreads();
    }

    // --- epilogue: rowscale / bias, store float2 pairs ---
#pragma unroll
    for (int im = 0; im < MF; im++) {
        int ra = row0 + warp_m * 32 + im * 16 + qid;
        int rb = ra + 8;
        float sa = 1.f, sb = 1.f;
        if (use_rowscale) {
            if (ra < N_NODES) sa = d_dinv[ra];
            if (rb < N_NODES) sb = d_dinv[rb];
        }
#pragma unroll
        for (int jn = 0; jn < NF; jn++) {
            int col = warp_n * WN + jn * 8 + qt * 2;
            float bx = 0.f, by = 0.f;
            if (bias) { bx = bias[col]; by = bias[col + 1]; }
            if (ra < N_NODES) {
                float2 o = make_float2(fmaf(acc[im][jn][0], sa, bx),
                                       fmaf(acc[im][jn][1], sa, by));
                *(float2*)&C[(size_t)ra * BN + col] = o;
            }
            if (rb < N_NODES) {
                float2 o = make_float2(fmaf(acc[im][jn][2], sb, bx),
                                       fmaf(acc[im][jn][3], sb, by));
                *(float2*)&C[(size_t)rb * BN + col] = o;
            }
        }
    }
}

// ---------------------------------------------------------------------------
// Aggregation: one warp per node. y[v] = relu(dinv[v]*(g[v] + sum g[u]) + b)
// ---------------------------------------------------------------------------
__global__ void agg_kernel(const float* __restrict__ bias) {
    int gw = (blockIdx.x * blockDim.x + threadIdx.x) >> 5;
    if (gw >= N_NODES) return;
    int lane = threadIdx.x & 31;
    int c = lane << 2;

    float4 acc = *(const float4*)&d_g[(size_t)gw * C_FEAT + c];  // self loop
    int s = d_off[gw], e = d_off[gw + 1];
    for (int base = s; base < e; base += 32) {
        int n = e - base;
        int m = n < 32 ? n : 32;
        int myu = (lane < m) ? d_adj[base + lane] : 0;
        for (int j = 0; j < m; j++) {
            int u = __shfl_sync(0xffffffffu, myu, j);
            float4 t = *(const float4*)&d_g[(size_t)u * C_FEAT + c];
            acc.x += t.x; acc.y += t.y; acc.z += t.z; acc.w += t.w;
        }
    }
    float dv = d_dinv[gw];
    float4 bb = *(const float4*)&bias[c];
    float4 o;
    o.x = fmaxf(fmaf(acc.x, dv, bb.x), 0.f);
    o.y = fmaxf(fmaf(acc.y, dv, bb.y), 0.f);
    o.z = fmaxf(fmaf(acc.z, dv, bb.z), 0.f);
    o.w = fmaxf(fmaf(acc.w, dv, bb.w), 0.f);
    *(float4*)&d_y[(size_t)gw * C_FEAT + c] = o;
}

// ---------------------------------------------------------------------------
extern "C" void kernel_launch(void* const* d_in, const int* in_sizes, int n_in,
                              void* d_out, int out_size) {
    const float* x  = (const float*)d_in[0];
    const int*   ei = (const int*)d_in[1];     // int32
    const float* W1 = (const float*)d_in[2];
    const float* b1 = (const float*)d_in[3];
    const float* W2 = (const float*)d_in[4];
    const float* b2 = (const float*)d_in[5];
    const float* Wl = (const float*)d_in[6];
    const float* bl = (const float*)d_in[7];
    float* out = (float*)d_out;

    int E = in_sizes[1] / 2;   // 640000

    // CSR build
    zero_cnt_kernel<<<(N_NODES + 255) / 256, 256>>>();
    hist_kernel<<<(E + 255) / 256, 256>>>(ei, E);
    scan_kernel<<<1, 1024>>>();
    scatter_kernel<<<(E + 255) / 256, 256>>>(ei, E);

    const int gemm_grid = (N_NODES + 127) / 128;        // 313
    const int agg_grid  = (N_NODES * 32 + 255) / 256;   // 5000

    // Layer 1
    gemm_tf32_kernel<128><<<gemm_grid, 256>>>(x, W1, nullptr, nullptr, 0, 1, 1);
    agg_kernel<<<agg_grid, 256>>>(b1);
    // Layer 2
    gemm_tf32_kernel<128><<<gemm_grid, 256>>>(nullptr, W2, nullptr, nullptr, 1, 1, 1);
    agg_kernel<<<agg_grid, 256>>>(b2);
    // Head
    gemm_tf32_kernel<64><<<gemm_grid, 256>>>(nullptr, Wl, bl, out, 1, 0, 0);
}